// round 11
// baseline (speedup 1.0000x reference)
#include <cuda_runtime.h>
#include <cstdint>
#include <math.h>

// Problem dims (fixed)
#define Bb 128
#define Tt 512
#define Hh 1024
#define BT (Bb*Tt)

// -------- device-global scratch ------------------------------------------
__device__ float g_xp[(size_t)BT * Hh];    // 256 MB input projections [T][B][H]
__device__ float g_hr[(size_t)BT * Hh];    // 256 MB rounded+permuted h [B][T][H]
__device__ float g_h[2][Bb * Hh];          // h double buffer (rounded+permuted)
__device__ float g_embr[1024 * 1024];      // rounded+permuted embed table
__device__ float g_Wxr[1024 * 1024];       // rounded+permuted Wx
__device__ float g_Wor[1024 * 1024];       // rounded+permuted Wo
__device__ unsigned int g_flag[128 * 32];  // per-CTA publish counters, 128B apart

// -------- helpers --------------------------------------------------------
__device__ __forceinline__ uint32_t f2t(float x) {
    uint32_t u; asm("cvt.rna.tf32.f32 %0, %1;" : "=r"(u) : "f"(x));
    return u;
}
__device__ __forceinline__ float rndt(float x) { return __uint_as_float(f2t(x)); }
// k-pair interleave within 8-blocks: (j, j+4) -> positions (2j, 2j+1)
__device__ __forceinline__ int pig(int k) {
    int j = k & 7;
    return (k & ~7) | ((j < 4) ? (2 * j) : (2 * (j - 4) + 1));
}
__device__ __forceinline__ void cp16(float* s, const float* g) {
    uint32_t sa = (uint32_t)__cvta_generic_to_shared(s);
    asm volatile("cp.async.cg.shared.global [%0], [%1], 16;\n" :: "r"(sa), "l"(g));
}
__device__ __forceinline__ void cp_commit() { asm volatile("cp.async.commit_group;\n"); }
template<int N> __device__ __forceinline__ void cp_wait() {
    asm volatile("cp.async.wait_group %0;\n" :: "n"(N));
}
__device__ __forceinline__ void mma8(float* c, const uint32_t* a, const uint32_t* b) {
    asm volatile(
        "mma.sync.aligned.m16n8k8.row.col.f32.tf32.tf32.f32 "
        "{%0,%1,%2,%3},{%4,%5,%6,%7},{%8,%9},{%0,%1,%2,%3};"
        : "+f"(c[0]), "+f"(c[1]), "+f"(c[2]), "+f"(c[3])
        : "r"(a[0]), "r"(a[1]), "r"(a[2]), "r"(a[3]), "r"(b[0]), "r"(b[1]));
}

// -------- prologue: round+permute embed, Wx, Wo --------------------------
__global__ void prep_k(const float* __restrict__ e, const float* __restrict__ wx,
                       const float* __restrict__ wo) {
    int st = gridDim.x * blockDim.x;
    for (int i = blockIdx.x * blockDim.x + threadIdx.x; i < 1024 * 1024; i += st) {
        int r = i >> 10, k = i & 1023;
        int d = (r << 10) | pig(k);
        g_embr[d] = rndt(e[i]);
        g_Wxr[d]  = rndt(wx[i]);
        g_Wor[d]  = rndt(wo[i]);
    }
}

__global__ void init_k(const float* __restrict__ h0) {
    int i = blockIdx.x * blockDim.x + threadIdx.x;
    if (i < 128) g_flag[i * 32] = 0u;
    for (int j = i; j < Bb * Hh; j += gridDim.x * blockDim.x) {
        int r = j >> 10, k = j & 1023;
        g_h[0][(r << 10) | pig(k)] = rndt(h0[j]);
    }
}

// -------- phase GEMM: C[m][n] = sum_k A[m][k]*W[n][k] + bias[n] ----------
// Tile 128(M) x 128(N) x 32(K), 256 threads = 8 warps (2M x 4N), warp 64x32.
// 4-stage cp.async ring, prefetch depth 3.
#define PS 44
#define TSZ 5632   // 128 rows x 44 per stage (A or B)

__device__ __forceinline__ void stage_p(const float* const* rp, const float* __restrict__ W,
                                        int n0, int k0, float* As, float* Bs, int tid) {
    #pragma unroll
    for (int j = 0; j < 4; j++) {                 // A: 128 rows x 32 floats
        int c = j * 256 + tid; int r = c >> 3, o = c & 7;
        cp16(As + r * PS + o * 4, rp[r] + k0 + o * 4);
    }
    #pragma unroll
    for (int j = 0; j < 4; j++) {                 // B: 128 rows x 32 floats
        int c = j * 256 + tid; int r = c >> 3, o = c & 7;
        cp16(Bs + r * PS + o * 4, W + (size_t)(n0 + r) * 1024 + k0 + o * 4);
    }
}

template<bool GATHER>
__global__ __launch_bounds__(256, 1) void gemm_k(const float* __restrict__ Ab,
                                                 const int* __restrict__ tok,
                                                 const float* __restrict__ W,
                                                 const float* __restrict__ bias,
                                                 float* __restrict__ C) {
    extern __shared__ float sm[];
    float* As = sm;                        // 4 x 5632
    float* Bs = sm + 4 * TSZ;              // 4 x 5632
    const float** rp = (const float**)(sm + 8 * TSZ);   // 128 ptrs

    const int tid = threadIdx.x;
    if (tid < 128) {
        if (GATHER) rp[tid] = Ab + (size_t)tok[tid * Tt + blockIdx.y] * 1024;
        else        rp[tid] = Ab + ((size_t)blockIdx.y * 128 + tid) * 1024;
    }
    __syncthreads();

    const int n0 = blockIdx.x * 128;
    const int lane = tid & 31, w = tid >> 5;
    const int g = lane >> 2, t4 = lane & 3;
    const int wm = (w >> 2) * 64, wn = (w & 3) * 32;

    float acc[4][4][4];
    #pragma unroll
    for (int a = 0; a < 4; a++)
        #pragma unroll
        for (int b = 0; b < 4; b++)
            #pragma unroll
            for (int c = 0; c < 4; c++) acc[a][b][c] = 0.f;

    stage_p(rp, W, n0, 0,  As,           Bs,           tid); cp_commit();
    stage_p(rp, W, n0, 32, As + TSZ,     Bs + TSZ,     tid); cp_commit();
    stage_p(rp, W, n0, 64, As + 2 * TSZ, Bs + 2 * TSZ, tid); cp_commit();

    for (int ks = 0; ks < 32; ks++) {
        if (ks < 30) cp_wait<2>(); else if (ks == 30) cp_wait<1>(); else cp_wait<0>();
        __syncthreads();
        if (ks < 29) {
            int nb = (ks + 3) & 3;
            stage_p(rp, W, n0, (ks + 3) * 32, As + nb * TSZ, Bs + nb * TSZ, tid);
            cp_commit();
        }
        const float* A_ = As + (ks & 3) * TSZ;
        const float* B_ = Bs + (ks & 3) * TSZ;
        #pragma unroll
        for (int kk = 0; kk < 32; kk += 8) {
            uint32_t a[4][4];
            #pragma unroll
            for (int mi = 0; mi < 4; mi++) {
                float2 p0 = *(const float2*)&A_[(wm + mi * 16 + g) * PS + kk + 2 * t4];
                float2 p1 = *(const float2*)&A_[(wm + mi * 16 + 8 + g) * PS + kk + 2 * t4];
                a[mi][0] = __float_as_uint(p0.x); a[mi][1] = __float_as_uint(p1.x);
                a[mi][2] = __float_as_uint(p0.y); a[mi][3] = __float_as_uint(p1.y);
            }
            #pragma unroll
            for (int ni = 0; ni < 4; ni++) {
                float2 q = *(const float2*)&B_[(wn + ni * 8 + g) * PS + kk + 2 * t4];
                uint32_t b[2] = { __float_as_uint(q.x), __float_as_uint(q.y) };
                #pragma unroll
                for (int mi = 0; mi < 4; mi++)
                    mma8(acc[mi][ni], a[mi], b);
            }
        }
    }

    const int m0 = blockIdx.y * 128;
    #pragma unroll
    for (int ni = 0; ni < 4; ni++) {
        int nc = n0 + wn + ni * 8 + 2 * t4;
        float b0 = bias[nc], b1 = bias[nc + 1];
        #pragma unroll
        for (int mi = 0; mi < 4; mi++) {
            int r0 = m0 + wm + mi * 16 + g;
            *(float2*)&C[(size_t)r0 * 1024 + nc] =
                make_float2(acc[mi][ni][0] + b0, acc[mi][ni][1] + b1);
            *(float2*)&C[(size_t)(r0 + 8) * 1024 + nc] =
                make_float2(acc[mi][ni][2] + b0, acc[mi][ni][3] + b1);
        }
    }
}

// -------- persistent recurrence kernel (v8) ------------------------------
// 128 CTAs = 4 independent M-groups x 32 N-CTAs, 256 thr (8 warps).
// Wh in registers; one-shot 4-chunk h staging; partials in own chunk-0.
// NEW: epilogue/staging overlap. After sync(A), warps 0-3 reduce, then
// bar.arrive(2,256); warps 4-7 poll their t+1 producer flags concurrently
// with the epilogue and bar.sync(2,256) (= reducer reads done) before
// staging. Warps 0-3 stage after bar1+release, with the DRAM stores and
// xp prefetch moved behind the staging issue. No trailing __syncthreads.
#define STG 36              // stage row stride (floats)
#define CHB (32 * STG)      // one chunk buffer = 1152 floats
#define CHW (4 * CHB)       // per-warp: 4 buffers = 4608 floats
#define SMEM_RF (8 * CHW)   // 36864 floats = 147456 B

__device__ __forceinline__ void stage_r(const float* gsrc, float* SB, int srow, int su) {
    #pragma unroll
    for (int cc = 0; cc < 4; cc++) {
        #pragma unroll
        for (int j = 0; j < 8; j++) {
            int r = srow + 4 * j;
            cp16(SB + cc * CHB + r * STG + su * 4,
                 gsrc + (size_t)r * 1024 + cc * 32 + su * 4);
        }
        cp_commit();
    }
}

__global__ __launch_bounds__(256, 1) void rnn_k(const float* __restrict__ Wh,
                                                const float* __restrict__ bh,
                                                float* __restrict__ h_e) {
    extern __shared__ float sm[];
    float* Stg = sm;                       // 8 warps x 4 x (32x36)

    const int tid = threadIdx.x;
    const int nq = blockIdx.x & 31, mq = blockIdx.x >> 5;
    const int nb = nq * 32, mb = mq * 32;

    const int lane = tid & 31, w = tid >> 5;
    const int g = lane >> 2, t4 = lane & 3;
    const int kb = w * 128;
    float* SB = Stg + w * CHW;
    const int srow = lane >> 3, su = lane & 7;

    // this warp's 4 producer flags (group mq, producers 4w..4w+3); lane<4 polls
    unsigned int* pflag = &g_flag[((mq << 5) | (4 * w + (lane & 3))) * 32];
    unsigned int* myflag = &g_flag[blockIdx.x * 32];

    // ---- load Wh B-fragments into registers (rounded RNA; once) ----
    uint32_t bfr[4][16][2];
    #pragma unroll
    for (int ni = 0; ni < 4; ni++) {
        const float* Wrow = Wh + (size_t)(nb + ni * 8 + g) * 1024 + kb + t4;
        #pragma unroll
        for (int kf = 0; kf < 16; kf++) {
            bfr[ni][kf][0] = f2t(Wrow[kf * 8]);
            bfr[ni][kf][1] = f2t(Wrow[kf * 8 + 4]);
        }
    }

    // epilogue mapping (tid<128): row er, cols [gcb, gcb+8)
    const int er = tid & 31, eblk = tid >> 5;
    const int gr = mb + er, gcb = nb + eblk * 8;
    float bhv[8];
    float4 xq0, xq1;
    if (tid < 128) {
        float4 q0 = *(const float4*)&bh[gcb];
        float4 q1 = *(const float4*)&bh[gcb + 4];
        bhv[0]=q0.x; bhv[1]=q0.y; bhv[2]=q0.z; bhv[3]=q0.w;
        bhv[4]=q1.x; bhv[5]=q1.y; bhv[6]=q1.z; bhv[7]=q1.w;
        xq0 = *(const float4*)&g_xp[(size_t)gr * 1024 + gcb];
        xq1 = *(const float4*)&g_xp[(size_t)gr * 1024 + gcb + 4];
    }

    // prologue: stage h(0) (published by init_k before this launch)
    stage_r(g_h[0] + (size_t)mb * 1024 + kb, SB, srow, su);

    for (int t = 0; t < Tt; t++) {
        // ---- mainloop: consume buffers staged last iteration ----
        float acc[2][4][4];
        #pragma unroll
        for (int a = 0; a < 2; a++)
            #pragma unroll
            for (int b = 0; b < 4; b++)
                #pragma unroll
                for (int c = 0; c < 4; c++) acc[a][b][c] = 0.f;

        #pragma unroll
        for (int c = 0; c < 4; c++) {
            if (c == 0) cp_wait<3>();
            else if (c == 1) cp_wait<2>();
            else if (c == 2) cp_wait<1>();
            else cp_wait<0>();
            __syncwarp();
            const float* B_ = SB + c * CHB;
            #pragma unroll
            for (int kf = 0; kf < 4; kf++) {
                uint32_t a[2][4];
                #pragma unroll
                for (int mi = 0; mi < 2; mi++) {
                    float2 p0 = *(const float2*)&B_[(mi * 16 + g) * STG + kf * 8 + 2 * t4];
                    float2 p1 = *(const float2*)&B_[(mi * 16 + 8 + g) * STG + kf * 8 + 2 * t4];
                    a[mi][0] = __float_as_uint(p0.x); a[mi][1] = __float_as_uint(p1.x);
                    a[mi][2] = __float_as_uint(p0.y); a[mi][3] = __float_as_uint(p1.y);
                }
                #pragma unroll
                for (int ni = 0; ni < 4; ni++) {
                    mma8(acc[0][ni], a[0], bfr[ni][c * 4 + kf]);
                    mma8(acc[1][ni], a[1], bfr[ni][c * 4 + kf]);
                }
            }
        }

        // K-partials into own chunk-0 buffer
        #pragma unroll
        for (int mi = 0; mi < 2; mi++)
            #pragma unroll
            for (int ni = 0; ni < 4; ni++) {
                int nc = ni * 8 + 2 * t4;
                *(float2*)&SB[(mi * 16 + g) * STG + nc] =
                    make_float2(acc[mi][ni][0], acc[mi][ni][1]);
                *(float2*)&SB[(mi * 16 + 8 + g) * STG + nc] =
                    make_float2(acc[mi][ni][2], acc[mi][ni][3]);
            }
        __syncthreads();   // (A) partials visible to reducers

        const float* nsrc = g_h[(t + 1) & 1] + (size_t)mb * 1024 + kb;

        if (tid < 128) {
            // ---- reducers: read partials, free the buffers, epilogue ----
            float s[8] = {0.f,0.f,0.f,0.f,0.f,0.f,0.f,0.f};
            #pragma unroll
            for (int ww = 0; ww < 8; ww++) {
                const float* Rr = Stg + ww * CHW + er * STG + eblk * 8;
                float4 r0 = *(const float4*)&Rr[0];
                float4 r1 = *(const float4*)&Rr[4];
                s[0] += r0.x; s[1] += r0.y; s[2] += r0.z; s[3] += r0.w;
                s[4] += r1.x; s[5] += r1.y; s[6] += r1.z; s[7] += r1.w;
            }
            // partial reads done -> let warps 4-7 proceed to staging
            asm volatile("bar.arrive 2, 256;" ::: "memory");

            float v[8], r[8];
            float* hd = g_h[(t + 1) & 1];
            v[0] = tanhf(s[0] + xq0.x + bhv[0]);
            v[1] = tanhf(s[1] + xq0.y + bhv[1]);
            v[2] = tanhf(s[2] + xq0.z + bhv[2]);
            v[3] = tanhf(s[3] + xq0.w + bhv[3]);
            v[4] = tanhf(s[4] + xq1.x + bhv[4]);
            v[5] = tanhf(s[5] + xq1.y + bhv[5]);
            v[6] = tanhf(s[6] + xq1.z + bhv[6]);
            v[7] = tanhf(s[7] + xq1.w + bhv[7]);
            #pragma unroll
            for (int j = 0; j < 8; j++) r[j] = rndt(v[j]);
            *(float4*)&hd[(size_t)gr * 1024 + gcb]     = make_float4(r[0], r[4], r[1], r[5]);
            *(float4*)&hd[(size_t)gr * 1024 + gcb + 4] = make_float4(r[2], r[6], r[3], r[7]);

            // named barrier over the 128 storing threads, then release own flag
            asm volatile("bar.sync 1, 128;" ::: "memory");
            if (tid == 0)
                asm volatile("red.release.gpu.global.add.u32 [%0], %1;"
                             :: "l"(myflag), "r"(1u) : "memory");

            // stage next step (own chunk-0 safe: bar1 = all reducer reads done)
            if (t + 1 < Tt) {
                if (lane < 4) {
                    unsigned tgt = (unsigned)(t + 1), vv;
                    do {
                        asm volatile("ld.acquire.gpu.u32 %0, [%1];" : "=r"(vv) : "l"(pflag));
                    } while (vv < tgt);
                }
                __syncwarp();
                stage_r(nsrc, SB, srow, su);
            }

            // DRAM stores + next xp prefetch: hidden under staging round trip
            size_t orow = ((size_t)gr * Tt + t) * 1024 + gcb;
            *(float4*)&h_e[orow]     = make_float4(v[0], v[1], v[2], v[3]);
            *(float4*)&h_e[orow + 4] = make_float4(v[4], v[5], v[6], v[7]);
            *(float4*)&g_hr[orow]     = make_float4(r[0], r[4], r[1], r[5]);
            *(float4*)&g_hr[orow + 4] = make_float4(r[2], r[6], r[3], r[7]);
            if (t + 1 < Tt) {
                xq0 = *(const float4*)&g_xp[(size_t)((t + 1) * 128 + gr) * 1024 + gcb];
                xq1 = *(const float4*)&g_xp[(size_t)((t + 1) * 128 + gr) * 1024 + gcb + 4];
            }
        } else {
            // ---- warps 4-7: poll producers DURING the epilogue ----
            if (t + 1 < Tt) {
                if (lane < 4) {
                    unsigned tgt = (unsigned)(t + 1), vv;
                    do {
                        asm volatile("ld.acquire.gpu.u32 %0, [%1];" : "=r"(vv) : "l"(pflag));
                    } while (vv < tgt);
                }
                __syncwarp();
            }
            // wait until reducers have read our chunk-0 partials
            asm volatile("bar.sync 2, 256;" ::: "memory");
            if (t + 1 < Tt) stage_r(nsrc, SB, srow, su);
        }
    }
}

// -------- launch ---------------------------------------------------------
extern "C" void kernel_launch(void* const* d_in, const int* in_sizes, int n_in,
                              void* d_out, int out_size) {
    (void)in_sizes; (void)n_in; (void)out_size;
    const int*   x      = (const int*)d_in[0];
    const float* h_init = (const float*)d_in[1];
    const float* embed  = (const float*)d_in[2];
    const float* Wx     = (const float*)d_in[3];
    const float* bx     = (const float*)d_in[4];
    const float* Wh     = (const float*)d_in[5];
    const float* bh     = (const float*)d_in[6];
    const float* Wo     = (const float*)d_in[7];
    const float* bo     = (const float*)d_in[8];

    float* out = (float*)d_out;
    float* h_e = out;                       // [B][T][H]
    float* y_e = out + (size_t)BT * Hh;     // [B][T][V]

    const int SMEM_P = 8 * TSZ * 4 + 128 * 8;               // 181248
    const int SMEM_R = SMEM_RF * 4;                         // 147456

    cudaFuncSetAttribute(gemm_k<true>,  cudaFuncAttributeMaxDynamicSharedMemorySize, SMEM_P);
    cudaFuncSetAttribute(gemm_k<false>, cudaFuncAttributeMaxDynamicSharedMemorySize, SMEM_P);
    cudaFuncSetAttribute(rnn_k,         cudaFuncAttributeMaxDynamicSharedMemorySize, SMEM_R);

    void* xp_ptr = nullptr;   cudaGetSymbolAddress(&xp_ptr, g_xp);
    void* hr_ptr = nullptr;   cudaGetSymbolAddress(&hr_ptr, g_hr);
    void* emb_ptr = nullptr;  cudaGetSymbolAddress(&emb_ptr, g_embr);
    void* wx_ptr = nullptr;   cudaGetSymbolAddress(&wx_ptr, g_Wxr);
    void* wo_ptr = nullptr;   cudaGetSymbolAddress(&wo_ptr, g_Wor);

    // 1. round+permute embed/Wx/Wo; reset flags; h_init -> g_h[0]
    prep_k<<<512, 256>>>(embed, Wx, Wo);
    init_k<<<128, 256>>>(h_init);
    // 2. xp[t][b][:] = embed_r[x[b][t]] @ Wx_r^T + bx
    gemm_k<true><<<dim3(8, 512), 256, SMEM_P>>>((const float*)emb_ptr, x,
                                                (const float*)wx_ptr, bx, (float*)xp_ptr);
    // 3. serial recurrence -> h_e (+ rounded copies)
    rnn_k<<<128, 256, SMEM_R>>>(Wh, bh, h_e);
    // 4. y = h_r @ Wo_r^T + bo
    gemm_k<false><<<dim3(8, 512), 256, SMEM_P>>>((const float*)hr_ptr, nullptr,
                                                 (const float*)wo_ptr, bo, y_e);
}

// round 12
// speedup vs baseline: 1.1414x; 1.1414x over previous
#include <cuda_runtime.h>
#include <cstdint>
#include <math.h>

// Problem dims (fixed)
#define Bb 128
#define Tt 512
#define Hh 1024
#define BT (Bb*Tt)

// -------- device-global scratch ------------------------------------------
__device__ float g_xp[(size_t)BT * Hh];    // 256 MB input projections [T][B][H]
__device__ float g_hr[(size_t)BT * Hh];    // 256 MB rounded+permuted h [B][T][H]
__device__ float g_h[2][Bb * Hh];          // h double buffer (rounded+permuted)
__device__ float g_embr[1024 * 1024];      // rounded+permuted embed table
__device__ float g_Wxr[1024 * 1024];       // rounded+permuted Wx
__device__ float g_Wor[1024 * 1024];       // rounded+permuted Wo
__device__ unsigned int g_flag[128 * 32];  // per-CTA publish counters, 128B apart

// -------- helpers --------------------------------------------------------
__device__ __forceinline__ uint32_t f2t(float x) {
    uint32_t u; asm("cvt.rna.tf32.f32 %0, %1;" : "=r"(u) : "f"(x));
    return u;
}
__device__ __forceinline__ float rndt(float x) { return __uint_as_float(f2t(x)); }
// k-pair interleave within 8-blocks: (j, j+4) -> positions (2j, 2j+1)
__device__ __forceinline__ int pig(int k) {
    int j = k & 7;
    return (k & ~7) | ((j < 4) ? (2 * j) : (2 * (j - 4) + 1));
}
__device__ __forceinline__ void cp16(float* s, const float* g) {
    uint32_t sa = (uint32_t)__cvta_generic_to_shared(s);
    asm volatile("cp.async.cg.shared.global [%0], [%1], 16;\n" :: "r"(sa), "l"(g));
}
__device__ __forceinline__ void cp_commit() { asm volatile("cp.async.commit_group;\n"); }
template<int N> __device__ __forceinline__ void cp_wait() {
    asm volatile("cp.async.wait_group %0;\n" :: "n"(N));
}
__device__ __forceinline__ void mma8(float* c, const uint32_t* a, const uint32_t* b) {
    asm volatile(
        "mma.sync.aligned.m16n8k8.row.col.f32.tf32.tf32.f32 "
        "{%0,%1,%2,%3},{%4,%5,%6,%7},{%8,%9},{%0,%1,%2,%3};"
        : "+f"(c[0]), "+f"(c[1]), "+f"(c[2]), "+f"(c[3])
        : "r"(a[0]), "r"(a[1]), "r"(a[2]), "r"(a[3]), "r"(b[0]), "r"(b[1]));
}

// -------- prologue: round+permute embed, Wx, Wo --------------------------
__global__ void prep_k(const float* __restrict__ e, const float* __restrict__ wx,
                       const float* __restrict__ wo) {
    int st = gridDim.x * blockDim.x;
    for (int i = blockIdx.x * blockDim.x + threadIdx.x; i < 1024 * 1024; i += st) {
        int r = i >> 10, k = i & 1023;
        int d = (r << 10) | pig(k);
        g_embr[d] = rndt(e[i]);
        g_Wxr[d]  = rndt(wx[i]);
        g_Wor[d]  = rndt(wo[i]);
    }
}

__global__ void init_k(const float* __restrict__ h0) {
    int i = blockIdx.x * blockDim.x + threadIdx.x;
    if (i < 128) g_flag[i * 32] = 0u;
    for (int j = i; j < Bb * Hh; j += gridDim.x * blockDim.x) {
        int r = j >> 10, k = j & 1023;
        g_h[0][(r << 10) | pig(k)] = rndt(h0[j]);
    }
}

// -------- phase GEMM: C[m][n] = sum_k A[m][k]*W[n][k] + bias[n] ----------
// Tile 128(M) x 128(N) x 32(K), 256 threads = 8 warps (2M x 4N), warp 64x32.
// 2-stage cp.async ring + occupancy 2: cross-CTA overlap hides the stage
// latency instead of deep prefetch (91 KB smem -> 2 CTAs/SM).
#define PS 44
#define TSZ 5632   // 128 rows x 44 per stage (A or B)

__device__ __forceinline__ void stage_p(const float* const* rp, const float* __restrict__ W,
                                        int n0, int k0, float* As, float* Bs, int tid) {
    #pragma unroll
    for (int j = 0; j < 4; j++) {                 // A: 128 rows x 32 floats
        int c = j * 256 + tid; int r = c >> 3, o = c & 7;
        cp16(As + r * PS + o * 4, rp[r] + k0 + o * 4);
    }
    #pragma unroll
    for (int j = 0; j < 4; j++) {                 // B: 128 rows x 32 floats
        int c = j * 256 + tid; int r = c >> 3, o = c & 7;
        cp16(Bs + r * PS + o * 4, W + (size_t)(n0 + r) * 1024 + k0 + o * 4);
    }
}

template<bool GATHER>
__global__ __launch_bounds__(256, 2) void gemm_k(const float* __restrict__ Ab,
                                                 const int* __restrict__ tok,
                                                 const float* __restrict__ W,
                                                 const float* __restrict__ bias,
                                                 float* __restrict__ C) {
    extern __shared__ float sm[];
    float* As = sm;                        // 2 x 5632
    float* Bs = sm + 2 * TSZ;              // 2 x 5632
    const float** rp = (const float**)(sm + 4 * TSZ);   // 128 ptrs

    const int tid = threadIdx.x;
    if (tid < 128) {
        if (GATHER) rp[tid] = Ab + (size_t)tok[tid * Tt + blockIdx.y] * 1024;
        else        rp[tid] = Ab + ((size_t)blockIdx.y * 128 + tid) * 1024;
    }
    __syncthreads();

    const int n0 = blockIdx.x * 128;
    const int lane = tid & 31, w = tid >> 5;
    const int g = lane >> 2, t4 = lane & 3;
    const int wm = (w >> 2) * 64, wn = (w & 3) * 32;

    float acc[4][4][4];
    #pragma unroll
    for (int a = 0; a < 4; a++)
        #pragma unroll
        for (int b = 0; b < 4; b++)
            #pragma unroll
            for (int c = 0; c < 4; c++) acc[a][b][c] = 0.f;

    stage_p(rp, W, n0, 0, As, Bs, tid);
    cp_commit();

    for (int ks = 0; ks < 32; ks++) {
        cp_wait<0>();
        __syncthreads();   // also orders: all reads of buf^1 done before restage
        if (ks < 31) {
            int nb = (ks + 1) & 1;
            stage_p(rp, W, n0, (ks + 1) * 32, As + nb * TSZ, Bs + nb * TSZ, tid);
            cp_commit();
        }
        const float* A_ = As + (ks & 1) * TSZ;
        const float* B_ = Bs + (ks & 1) * TSZ;
        #pragma unroll
        for (int kk = 0; kk < 32; kk += 8) {
            uint32_t a[4][4];
            #pragma unroll
            for (int mi = 0; mi < 4; mi++) {
                float2 p0 = *(const float2*)&A_[(wm + mi * 16 + g) * PS + kk + 2 * t4];
                float2 p1 = *(const float2*)&A_[(wm + mi * 16 + 8 + g) * PS + kk + 2 * t4];
                a[mi][0] = __float_as_uint(p0.x); a[mi][1] = __float_as_uint(p1.x);
                a[mi][2] = __float_as_uint(p0.y); a[mi][3] = __float_as_uint(p1.y);
            }
            #pragma unroll
            for (int ni = 0; ni < 4; ni++) {
                float2 q = *(const float2*)&B_[(wn + ni * 8 + g) * PS + kk + 2 * t4];
                uint32_t b[2] = { __float_as_uint(q.x), __float_as_uint(q.y) };
                #pragma unroll
                for (int mi = 0; mi < 4; mi++)
                    mma8(acc[mi][ni], a[mi], b);
            }
        }
    }

    const int m0 = blockIdx.y * 128;
    #pragma unroll
    for (int ni = 0; ni < 4; ni++) {
        int nc = n0 + wn + ni * 8 + 2 * t4;
        float b0 = bias[nc], b1 = bias[nc + 1];
        #pragma unroll
        for (int mi = 0; mi < 4; mi++) {
            int r0 = m0 + wm + mi * 16 + g;
            *(float2*)&C[(size_t)r0 * 1024 + nc] =
                make_float2(acc[mi][ni][0] + b0, acc[mi][ni][1] + b1);
            *(float2*)&C[(size_t)(r0 + 8) * 1024 + nc] =
                make_float2(acc[mi][ni][2] + b0, acc[mi][ni][3] + b1);
        }
    }
}

// -------- persistent recurrence kernel (v7 — REVERTED to R10 best) -------
// 128 CTAs = 4 independent M-groups x 32 N-CTAs, 256 thr (8 warps).
// Wh in registers; one-shot 4-chunk h staging; partials in own chunk-0.
// Decentralized hand-off: each CTA releases its OWN flag (named bar over
// the 128 epilogue threads + tid0 red.release); each consumer warp
// acquire-polls only its 4 producer CTAs (lanes 0-3) before staging.
#define STG 36              // stage row stride (floats)
#define CHB (32 * STG)      // one chunk buffer = 1152 floats
#define CHW (4 * CHB)       // per-warp: 4 buffers = 4608 floats
#define SMEM_RF (8 * CHW)   // 36864 floats = 147456 B

__global__ __launch_bounds__(256, 1) void rnn_k(const float* __restrict__ Wh,
                                                const float* __restrict__ bh,
                                                float* __restrict__ h_e) {
    extern __shared__ float sm[];
    float* Stg = sm;                       // 8 warps x 4 x (32x36)

    const int tid = threadIdx.x;
    const int nq = blockIdx.x & 31, mq = blockIdx.x >> 5;
    const int nb = nq * 32, mb = mq * 32;

    const int lane = tid & 31, w = tid >> 5;
    const int g = lane >> 2, t4 = lane & 3;
    const int kb = w * 128;
    float* SB = Stg + w * CHW;
    const int srow = lane >> 3, su = lane & 7;

    // this warp's 4 producer flags (group mq, producers 4w..4w+3); lane<4 polls
    unsigned int* pflag = &g_flag[((mq << 5) | (4 * w + (lane & 3))) * 32];
    unsigned int* myflag = &g_flag[blockIdx.x * 32];

    // ---- load Wh B-fragments into registers (rounded RNA; once) ----
    uint32_t bfr[4][16][2];
    #pragma unroll
    for (int ni = 0; ni < 4; ni++) {
        const float* Wrow = Wh + (size_t)(nb + ni * 8 + g) * 1024 + kb + t4;
        #pragma unroll
        for (int kf = 0; kf < 16; kf++) {
            bfr[ni][kf][0] = f2t(Wrow[kf * 8]);
            bfr[ni][kf][1] = f2t(Wrow[kf * 8 + 4]);
        }
    }

    // epilogue mapping (tid<128): row er, cols [gcb, gcb+8)
    const int er = tid & 31, eblk = tid >> 5;
    const int gr = mb + er, gcb = nb + eblk * 8;
    float bhv[8];
    float4 xq0, xq1;
    if (tid < 128) {
        float4 q0 = *(const float4*)&bh[gcb];
        float4 q1 = *(const float4*)&bh[gcb + 4];
        bhv[0]=q0.x; bhv[1]=q0.y; bhv[2]=q0.z; bhv[3]=q0.w;
        bhv[4]=q1.x; bhv[5]=q1.y; bhv[6]=q1.z; bhv[7]=q1.w;
        xq0 = *(const float4*)&g_xp[(size_t)gr * 1024 + gcb];
        xq1 = *(const float4*)&g_xp[(size_t)gr * 1024 + gcb + 4];
    }
    __syncthreads();

    for (int t = 0; t < Tt; t++) {
        const float* hs = g_h[t & 1];
        float* hd = g_h[(t + 1) & 1];
        const float* gsrc = hs + (size_t)mb * 1024 + kb;

        // acquire this warp's 4 producers (flag >= t means h(t) published)
        if (t > 0 && lane < 4) {
            unsigned tgt = (unsigned)t, vv;
            do {
                asm volatile("ld.acquire.gpu.u32 %0, [%1];" : "=r"(vv) : "l"(pflag));
            } while (vv < tgt);
        }
        __syncwarp();

        float acc[2][4][4];
        #pragma unroll
        for (int a = 0; a < 2; a++)
            #pragma unroll
            for (int b = 0; b < 4; b++)
                #pragma unroll
                for (int c = 0; c < 4; c++) acc[a][b][c] = 0.f;

        // stage ALL 4 chunks now (one L2 round trip, 4 commit groups)
        #pragma unroll
        for (int cc = 0; cc < 4; cc++) {
            #pragma unroll
            for (int j = 0; j < 8; j++) {
                int r = srow + 4 * j;
                cp16(SB + cc * CHB + r * STG + su * 4,
                     gsrc + (size_t)r * 1024 + cc * 32 + su * 4);
            }
            cp_commit();
        }

        #pragma unroll
        for (int c = 0; c < 4; c++) {
            if (c == 0) cp_wait<3>();
            else if (c == 1) cp_wait<2>();
            else if (c == 2) cp_wait<1>();
            else cp_wait<0>();
            __syncwarp();
            const float* B_ = SB + c * CHB;
            #pragma unroll
            for (int kf = 0; kf < 4; kf++) {
                uint32_t a[2][4];
                #pragma unroll
                for (int mi = 0; mi < 2; mi++) {
                    float2 p0 = *(const float2*)&B_[(mi * 16 + g) * STG + kf * 8 + 2 * t4];
                    float2 p1 = *(const float2*)&B_[(mi * 16 + 8 + g) * STG + kf * 8 + 2 * t4];
                    a[mi][0] = __float_as_uint(p0.x); a[mi][1] = __float_as_uint(p1.x);
                    a[mi][2] = __float_as_uint(p0.y); a[mi][3] = __float_as_uint(p1.y);
                }
                #pragma unroll
                for (int ni = 0; ni < 4; ni++) {
                    mma8(acc[0][ni], a[0], bfr[ni][c * 4 + kf]);
                    mma8(acc[1][ni], a[1], bfr[ni][c * 4 + kf]);
                }
            }
        }

        // K-partials into own chunk-0 buffer (first consumed; warp-private)
        #pragma unroll
        for (int mi = 0; mi < 2; mi++)
            #pragma unroll
            for (int ni = 0; ni < 4; ni++) {
                int nc = ni * 8 + 2 * t4;
                *(float2*)&SB[(mi * 16 + g) * STG + nc] =
                    make_float2(acc[mi][ni][0], acc[mi][ni][1]);
                *(float2*)&SB[(mi * 16 + 8 + g) * STG + nc] =
                    make_float2(acc[mi][ni][2], acc[mi][ni][3]);
            }
        __syncthreads();   // (A) partials visible to reducing warps

        // reduce 8 partials + tanh; store NEXT-STATE hd; publish own flag
        float v[8], r[8];
        if (tid < 128) {
            float s[8] = {0.f,0.f,0.f,0.f,0.f,0.f,0.f,0.f};
            #pragma unroll
            for (int ww = 0; ww < 8; ww++) {
                const float* Rr = Stg + ww * CHW + er * STG + eblk * 8;
                float4 r0 = *(const float4*)&Rr[0];
                float4 r1 = *(const float4*)&Rr[4];
                s[0] += r0.x; s[1] += r0.y; s[2] += r0.z; s[3] += r0.w;
                s[4] += r1.x; s[5] += r1.y; s[6] += r1.z; s[7] += r1.w;
            }
            v[0] = tanhf(s[0] + xq0.x + bhv[0]);
            v[1] = tanhf(s[1] + xq0.y + bhv[1]);
            v[2] = tanhf(s[2] + xq0.z + bhv[2]);
            v[3] = tanhf(s[3] + xq0.w + bhv[3]);
            v[4] = tanhf(s[4] + xq1.x + bhv[4]);
            v[5] = tanhf(s[5] + xq1.y + bhv[5]);
            v[6] = tanhf(s[6] + xq1.z + bhv[6]);
            v[7] = tanhf(s[7] + xq1.w + bhv[7]);
            #pragma unroll
            for (int j = 0; j < 8; j++) r[j] = rndt(v[j]);
            *(float4*)&hd[(size_t)gr * 1024 + gcb]     = make_float4(r[0], r[4], r[1], r[5]);
            *(float4*)&hd[(size_t)gr * 1024 + gcb + 4] = make_float4(r[2], r[6], r[3], r[7]);

            // named barrier over the 128 storing threads, then release own flag
            asm volatile("bar.sync 1, 128;" ::: "memory");
            if (tid == 0)
                asm volatile("red.release.gpu.global.add.u32 [%0], %1;"
                             :: "l"(myflag), "r"(1u) : "memory");

            // stores nobody consumes this step + next xp prefetch
            size_t orow = ((size_t)gr * Tt + t) * 1024 + gcb;
            *(float4*)&h_e[orow]     = make_float4(v[0], v[1], v[2], v[3]);
            *(float4*)&h_e[orow + 4] = make_float4(v[4], v[5], v[6], v[7]);
            *(float4*)&g_hr[orow]     = make_float4(r[0], r[4], r[1], r[5]);
            *(float4*)&g_hr[orow + 4] = make_float4(r[2], r[6], r[3], r[7]);
            if (t + 1 < Tt) {
                xq0 = *(const float4*)&g_xp[(size_t)((t + 1) * 128 + gr) * 1024 + gcb];
                xq1 = *(const float4*)&g_xp[(size_t)((t + 1) * 128 + gr) * 1024 + gcb + 4];
            }
        }
        __syncthreads();   // (B) reduce reads done -> chunk buffers reusable
    }
}

// -------- launch ---------------------------------------------------------
extern "C" void kernel_launch(void* const* d_in, const int* in_sizes, int n_in,
                              void* d_out, int out_size) {
    (void)in_sizes; (void)n_in; (void)out_size;
    const int*   x      = (const int*)d_in[0];
    const float* h_init = (const float*)d_in[1];
    const float* embed  = (const float*)d_in[2];
    const float* Wx     = (const float*)d_in[3];
    const float* bx     = (const float*)d_in[4];
    const float* Wh     = (const float*)d_in[5];
    const float* bh     = (const float*)d_in[6];
    const float* Wo     = (const float*)d_in[7];
    const float* bo     = (const float*)d_in[8];

    float* out = (float*)d_out;
    float* h_e = out;                       // [B][T][H]
    float* y_e = out + (size_t)BT * Hh;     // [B][T][V]

    const int SMEM_P = 4 * TSZ * 4 + 128 * 8;               // 90112 + 1024 = 91136
    const int SMEM_R = SMEM_RF * 4;                         // 147456

    cudaFuncSetAttribute(gemm_k<true>,  cudaFuncAttributeMaxDynamicSharedMemorySize, SMEM_P);
    cudaFuncSetAttribute(gemm_k<false>, cudaFuncAttributeMaxDynamicSharedMemorySize, SMEM_P);
    cudaFuncSetAttribute(rnn_k,         cudaFuncAttributeMaxDynamicSharedMemorySize, SMEM_R);

    void* xp_ptr = nullptr;   cudaGetSymbolAddress(&xp_ptr, g_xp);
    void* hr_ptr = nullptr;   cudaGetSymbolAddress(&hr_ptr, g_hr);
    void* emb_ptr = nullptr;  cudaGetSymbolAddress(&emb_ptr, g_embr);
    void* wx_ptr = nullptr;   cudaGetSymbolAddress(&wx_ptr, g_Wxr);
    void* wo_ptr = nullptr;   cudaGetSymbolAddress(&wo_ptr, g_Wor);

    // 1. round+permute embed/Wx/Wo; reset flags; h_init -> g_h[0]
    prep_k<<<512, 256>>>(embed, Wx, Wo);
    init_k<<<128, 256>>>(h_init);
    // 2. xp[t][b][:] = embed_r[x[b][t]] @ Wx_r^T + bx
    gemm_k<true><<<dim3(8, 512), 256, SMEM_P>>>((const float*)emb_ptr, x,
                                                (const float*)wx_ptr, bx, (float*)xp_ptr);
    // 3. serial recurrence -> h_e (+ rounded copies)
    rnn_k<<<128, 256, SMEM_R>>>(Wh, bh, h_e);
    // 4. y = h_r @ Wo_r^T + bo
    gemm_k<false><<<dim3(8, 512), 256, SMEM_P>>>((const float*)hr_ptr, nullptr,
                                                 (const float*)wo_ptr, bo, y_e);
}

// round 13
// speedup vs baseline: 1.1512x; 1.0086x over previous
#include <cuda_runtime.h>
#include <cstdint>
#include <math.h>

// Problem dims (fixed)
#define Bb 128
#define Tt 512
#define Hh 1024
#define BT (Bb*Tt)

// -------- device-global scratch ------------------------------------------
__device__ float g_xp[(size_t)BT * Hh];    // 256 MB input projections [T][B][H] (incl. bx+bh)
__device__ float g_hr[(size_t)BT * Hh];    // 256 MB rounded+permuted h [B][T][H]
__device__ float g_h[2][Bb * Hh];          // h double buffer (rounded+permuted)
__device__ float g_embr[1024 * 1024];      // rounded+permuted embed table
__device__ float g_Wxr[1024 * 1024];       // rounded+permuted Wx
__device__ float g_Wor[1024 * 1024];       // rounded+permuted Wo
__device__ float g_bsum[1024];             // bx + bh (fused step bias)
__device__ unsigned int g_flag[128 * 32];  // per-CTA publish counters, 128B apart

// -------- helpers --------------------------------------------------------
__device__ __forceinline__ uint32_t f2t(float x) {
    uint32_t u; asm("cvt.rna.tf32.f32 %0, %1;" : "=r"(u) : "f"(x));
    return u;
}
__device__ __forceinline__ float rndt(float x) { return __uint_as_float(f2t(x)); }
// k-pair interleave within 8-blocks: (j, j+4) -> positions (2j, 2j+1)
__device__ __forceinline__ int pig(int k) {
    int j = k & 7;
    return (k & ~7) | ((j < 4) ? (2 * j) : (2 * (j - 4) + 1));
}
__device__ __forceinline__ void cp16(float* s, const float* g) {
    uint32_t sa = (uint32_t)__cvta_generic_to_shared(s);
    asm volatile("cp.async.cg.shared.global [%0], [%1], 16;\n" :: "r"(sa), "l"(g));
}
__device__ __forceinline__ void cp_commit() { asm volatile("cp.async.commit_group;\n"); }
template<int N> __device__ __forceinline__ void cp_wait() {
    asm volatile("cp.async.wait_group %0;\n" :: "n"(N));
}
__device__ __forceinline__ void mma8(float* c, const uint32_t* a, const uint32_t* b) {
    asm volatile(
        "mma.sync.aligned.m16n8k8.row.col.f32.tf32.tf32.f32 "
        "{%0,%1,%2,%3},{%4,%5,%6,%7},{%8,%9},{%0,%1,%2,%3};"
        : "+f"(c[0]), "+f"(c[1]), "+f"(c[2]), "+f"(c[3])
        : "r"(a[0]), "r"(a[1]), "r"(a[2]), "r"(a[3]), "r"(b[0]), "r"(b[1]));
}
// fast tanh: 1 - 2/(exp(2x)+1) via ex2/rcp approx (saturates to +-1 at inf)
__device__ __forceinline__ float ftanh(float x) {
    float e;
    asm("ex2.approx.ftz.f32 %0, %1;" : "=f"(e) : "f"(x * 2.885390081777927f));
    float rc;
    asm("rcp.approx.ftz.f32 %0, %1;" : "=f"(rc) : "f"(e + 1.0f));
    return fmaf(-2.0f, rc, 1.0f);
}

// -------- prologue: round+permute embed, Wx, Wo --------------------------
__global__ void prep_k(const float* __restrict__ e, const float* __restrict__ wx,
                       const float* __restrict__ wo) {
    int st = gridDim.x * blockDim.x;
    for (int i = blockIdx.x * blockDim.x + threadIdx.x; i < 1024 * 1024; i += st) {
        int r = i >> 10, k = i & 1023;
        int d = (r << 10) | pig(k);
        g_embr[d] = rndt(e[i]);
        g_Wxr[d]  = rndt(wx[i]);
        g_Wor[d]  = rndt(wo[i]);
    }
}

__global__ void init_k(const float* __restrict__ h0, const float* __restrict__ bx,
                       const float* __restrict__ bh) {
    int i = blockIdx.x * blockDim.x + threadIdx.x;
    if (i < 128) g_flag[i * 32] = 0u;
    if (i < 1024) g_bsum[i] = bx[i] + bh[i];
    for (int j = i; j < Bb * Hh; j += gridDim.x * blockDim.x) {
        int r = j >> 10, k = j & 1023;
        g_h[0][(r << 10) | pig(k)] = rndt(h0[j]);
    }
}

// -------- phase GEMM: C[m][n] = sum_k A[m][k]*W[n][k] + bias[n] ----------
// Tile 128(M) x 128(N) x 32(K), 256 threads = 8 warps (2M x 4N), warp 64x32.
// 2-stage cp.async ring + occupancy 2 (cross-CTA overlap hides stage latency).
#define PS 44
#define TSZ 5632   // 128 rows x 44 per stage (A or B)

__device__ __forceinline__ void stage_p(const float* const* rp, const float* __restrict__ W,
                                        int n0, int k0, float* As, float* Bs, int tid) {
    #pragma unroll
    for (int j = 0; j < 4; j++) {                 // A: 128 rows x 32 floats
        int c = j * 256 + tid; int r = c >> 3, o = c & 7;
        cp16(As + r * PS + o * 4, rp[r] + k0 + o * 4);
    }
    #pragma unroll
    for (int j = 0; j < 4; j++) {                 // B: 128 rows x 32 floats
        int c = j * 256 + tid; int r = c >> 3, o = c & 7;
        cp16(Bs + r * PS + o * 4, W + (size_t)(n0 + r) * 1024 + k0 + o * 4);
    }
}

template<bool GATHER>
__global__ __launch_bounds__(256, 2) void gemm_k(const float* __restrict__ Ab,
                                                 const int* __restrict__ tok,
                                                 const float* __restrict__ W,
                                                 const float* __restrict__ bias,
                                                 float* __restrict__ C) {
    extern __shared__ float sm[];
    float* As = sm;                        // 2 x 5632
    float* Bs = sm + 2 * TSZ;              // 2 x 5632
    const float** rp = (const float**)(sm + 4 * TSZ);   // 128 ptrs

    const int tid = threadIdx.x;
    if (tid < 128) {
        if (GATHER) rp[tid] = Ab + (size_t)tok[tid * Tt + blockIdx.y] * 1024;
        else        rp[tid] = Ab + ((size_t)blockIdx.y * 128 + tid) * 1024;
    }
    __syncthreads();

    const int n0 = blockIdx.x * 128;
    const int lane = tid & 31, w = tid >> 5;
    const int g = lane >> 2, t4 = lane & 3;
    const int wm = (w >> 2) * 64, wn = (w & 3) * 32;

    float acc[4][4][4];
    #pragma unroll
    for (int a = 0; a < 4; a++)
        #pragma unroll
        for (int b = 0; b < 4; b++)
            #pragma unroll
            for (int c = 0; c < 4; c++) acc[a][b][c] = 0.f;

    stage_p(rp, W, n0, 0, As, Bs, tid);
    cp_commit();

    for (int ks = 0; ks < 32; ks++) {
        cp_wait<0>();
        __syncthreads();   // also orders: all reads of buf^1 done before restage
        if (ks < 31) {
            int nb = (ks + 1) & 1;
            stage_p(rp, W, n0, (ks + 1) * 32, As + nb * TSZ, Bs + nb * TSZ, tid);
            cp_commit();
        }
        const float* A_ = As + (ks & 1) * TSZ;
        const float* B_ = Bs + (ks & 1) * TSZ;
        #pragma unroll
        for (int kk = 0; kk < 32; kk += 8) {
            uint32_t a[4][4];
            #pragma unroll
            for (int mi = 0; mi < 4; mi++) {
                float2 p0 = *(const float2*)&A_[(wm + mi * 16 + g) * PS + kk + 2 * t4];
                float2 p1 = *(const float2*)&A_[(wm + mi * 16 + 8 + g) * PS + kk + 2 * t4];
                a[mi][0] = __float_as_uint(p0.x); a[mi][1] = __float_as_uint(p1.x);
                a[mi][2] = __float_as_uint(p0.y); a[mi][3] = __float_as_uint(p1.y);
            }
            #pragma unroll
            for (int ni = 0; ni < 4; ni++) {
                float2 q = *(const float2*)&B_[(wn + ni * 8 + g) * PS + kk + 2 * t4];
                uint32_t b[2] = { __float_as_uint(q.x), __float_as_uint(q.y) };
                #pragma unroll
                for (int mi = 0; mi < 4; mi++)
                    mma8(acc[mi][ni], a[mi], b);
            }
        }
    }

    const int m0 = blockIdx.y * 128;
    #pragma unroll
    for (int ni = 0; ni < 4; ni++) {
        int nc = n0 + wn + ni * 8 + 2 * t4;
        float b0 = bias[nc], b1 = bias[nc + 1];
        #pragma unroll
        for (int mi = 0; mi < 4; mi++) {
            int r0 = m0 + wm + mi * 16 + g;
            *(float2*)&C[(size_t)r0 * 1024 + nc] =
                make_float2(acc[mi][ni][0] + b0, acc[mi][ni][1] + b1);
            *(float2*)&C[(size_t)(r0 + 8) * 1024 + nc] =
                make_float2(acc[mi][ni][2] + b0, acc[mi][ni][3] + b1);
        }
    }
}

// -------- persistent recurrence kernel (v9 = R10 structure + fast tanh) ---
// 128 CTAs = 4 independent M-groups x 32 N-CTAs, 256 thr (8 warps).
// Wh in registers; one-shot 4-chunk h staging; partials in own chunk-0.
// Decentralized hand-off (per-CTA flags, per-warp producer acquire).
// Step bias (bx+bh) pre-fused into g_xp; tanh via ex2/rcp approx.
#define STG 36              // stage row stride (floats)
#define CHB (32 * STG)      // one chunk buffer = 1152 floats
#define CHW (4 * CHB)       // per-warp: 4 buffers = 4608 floats
#define SMEM_RF (8 * CHW)   // 36864 floats = 147456 B

__global__ __launch_bounds__(256, 1) void rnn_k(const float* __restrict__ Wh,
                                                float* __restrict__ h_e) {
    extern __shared__ float sm[];
    float* Stg = sm;                       // 8 warps x 4 x (32x36)

    const int tid = threadIdx.x;
    const int nq = blockIdx.x & 31, mq = blockIdx.x >> 5;
    const int nb = nq * 32, mb = mq * 32;

    const int lane = tid & 31, w = tid >> 5;
    const int g = lane >> 2, t4 = lane & 3;
    const int kb = w * 128;
    float* SB = Stg + w * CHW;
    const int srow = lane >> 3, su = lane & 7;

    // this warp's 4 producer flags (group mq, producers 4w..4w+3); lane<4 polls
    unsigned int* pflag = &g_flag[((mq << 5) | (4 * w + (lane & 3))) * 32];
    unsigned int* myflag = &g_flag[blockIdx.x * 32];

    // ---- load Wh B-fragments into registers (rounded RNA; once) ----
    uint32_t bfr[4][16][2];
    #pragma unroll
    for (int ni = 0; ni < 4; ni++) {
        const float* Wrow = Wh + (size_t)(nb + ni * 8 + g) * 1024 + kb + t4;
        #pragma unroll
        for (int kf = 0; kf < 16; kf++) {
            bfr[ni][kf][0] = f2t(Wrow[kf * 8]);
            bfr[ni][kf][1] = f2t(Wrow[kf * 8 + 4]);
        }
    }

    // epilogue mapping (tid<128): row er, cols [gcb, gcb+8)
    const int er = tid & 31, eblk = tid >> 5;
    const int gr = mb + er, gcb = nb + eblk * 8;
    float4 xq0, xq1;
    if (tid < 128) {
        xq0 = *(const float4*)&g_xp[(size_t)gr * 1024 + gcb];
        xq1 = *(const float4*)&g_xp[(size_t)gr * 1024 + gcb + 4];
    }
    __syncthreads();

    for (int t = 0; t < Tt; t++) {
        const float* hs = g_h[t & 1];
        float* hd = g_h[(t + 1) & 1];
        const float* gsrc = hs + (size_t)mb * 1024 + kb;

        // acquire this warp's 4 producers (flag >= t means h(t) published)
        if (t > 0 && lane < 4) {
            unsigned tgt = (unsigned)t, vv;
            do {
                asm volatile("ld.acquire.gpu.u32 %0, [%1];" : "=r"(vv) : "l"(pflag));
            } while (vv < tgt);
        }
        __syncwarp();

        float acc[2][4][4];
        #pragma unroll
        for (int a = 0; a < 2; a++)
            #pragma unroll
            for (int b = 0; b < 4; b++)
                #pragma unroll
                for (int c = 0; c < 4; c++) acc[a][b][c] = 0.f;

        // stage ALL 4 chunks now (one L2 round trip, 4 commit groups)
        #pragma unroll
        for (int cc = 0; cc < 4; cc++) {
            #pragma unroll
            for (int j = 0; j < 8; j++) {
                int r = srow + 4 * j;
                cp16(SB + cc * CHB + r * STG + su * 4,
                     gsrc + (size_t)r * 1024 + cc * 32 + su * 4);
            }
            cp_commit();
        }

        #pragma unroll
        for (int c = 0; c < 4; c++) {
            if (c == 0) cp_wait<3>();
            else if (c == 1) cp_wait<2>();
            else if (c == 2) cp_wait<1>();
            else cp_wait<0>();
            __syncwarp();
            const float* B_ = SB + c * CHB;
            #pragma unroll
            for (int kf = 0; kf < 4; kf++) {
                uint32_t a[2][4];
                #pragma unroll
                for (int mi = 0; mi < 2; mi++) {
                    float2 p0 = *(const float2*)&B_[(mi * 16 + g) * STG + kf * 8 + 2 * t4];
                    float2 p1 = *(const float2*)&B_[(mi * 16 + 8 + g) * STG + kf * 8 + 2 * t4];
                    a[mi][0] = __float_as_uint(p0.x); a[mi][1] = __float_as_uint(p1.x);
                    a[mi][2] = __float_as_uint(p0.y); a[mi][3] = __float_as_uint(p1.y);
                }
                #pragma unroll
                for (int ni = 0; ni < 4; ni++) {
                    mma8(acc[0][ni], a[0], bfr[ni][c * 4 + kf]);
                    mma8(acc[1][ni], a[1], bfr[ni][c * 4 + kf]);
                }
            }
        }

        // K-partials into own chunk-0 buffer (first consumed; warp-private)
        #pragma unroll
        for (int mi = 0; mi < 2; mi++)
            #pragma unroll
            for (int ni = 0; ni < 4; ni++) {
                int nc = ni * 8 + 2 * t4;
                *(float2*)&SB[(mi * 16 + g) * STG + nc] =
                    make_float2(acc[mi][ni][0], acc[mi][ni][1]);
                *(float2*)&SB[(mi * 16 + 8 + g) * STG + nc] =
                    make_float2(acc[mi][ni][2], acc[mi][ni][3]);
            }
        __syncthreads();   // (A) partials visible to reducing warps

        // reduce 8 partials + fast tanh; store NEXT-STATE hd; publish own flag
        float v[8], r[8];
        if (tid < 128) {
            float s[8] = {0.f,0.f,0.f,0.f,0.f,0.f,0.f,0.f};
            #pragma unroll
            for (int ww = 0; ww < 8; ww++) {
                const float* Rr = Stg + ww * CHW + er * STG + eblk * 8;
                float4 r0 = *(const float4*)&Rr[0];
                float4 r1 = *(const float4*)&Rr[4];
                s[0] += r0.x; s[1] += r0.y; s[2] += r0.z; s[3] += r0.w;
                s[4] += r1.x; s[5] += r1.y; s[6] += r1.z; s[7] += r1.w;
            }
            v[0] = ftanh(s[0] + xq0.x);
            v[1] = ftanh(s[1] + xq0.y);
            v[2] = ftanh(s[2] + xq0.z);
            v[3] = ftanh(s[3] + xq0.w);
            v[4] = ftanh(s[4] + xq1.x);
            v[5] = ftanh(s[5] + xq1.y);
            v[6] = ftanh(s[6] + xq1.z);
            v[7] = ftanh(s[7] + xq1.w);
            #pragma unroll
            for (int j = 0; j < 8; j++) r[j] = rndt(v[j]);
            *(float4*)&hd[(size_t)gr * 1024 + gcb]     = make_float4(r[0], r[4], r[1], r[5]);
            *(float4*)&hd[(size_t)gr * 1024 + gcb + 4] = make_float4(r[2], r[6], r[3], r[7]);

            // named barrier over the 128 storing threads, then release own flag
            asm volatile("bar.sync 1, 128;" ::: "memory");
            if (tid == 0)
                asm volatile("red.release.gpu.global.add.u32 [%0], %1;"
                             :: "l"(myflag), "r"(1u) : "memory");

            // stores nobody consumes this step + next xp prefetch
            size_t orow = ((size_t)gr * Tt + t) * 1024 + gcb;
            *(float4*)&h_e[orow]     = make_float4(v[0], v[1], v[2], v[3]);
            *(float4*)&h_e[orow + 4] = make_float4(v[4], v[5], v[6], v[7]);
            *(float4*)&g_hr[orow]     = make_float4(r[0], r[4], r[1], r[5]);
            *(float4*)&g_hr[orow + 4] = make_float4(r[2], r[6], r[3], r[7]);
            if (t + 1 < Tt) {
                xq0 = *(const float4*)&g_xp[(size_t)((t + 1) * 128 + gr) * 1024 + gcb];
                xq1 = *(const float4*)&g_xp[(size_t)((t + 1) * 128 + gr) * 1024 + gcb + 4];
            }
        }
        __syncthreads();   // (B) reduce reads done -> chunk buffers reusable
    }
}

// -------- launch ---------------------------------------------------------
extern "C" void kernel_launch(void* const* d_in, const int* in_sizes, int n_in,
                              void* d_out, int out_size) {
    (void)in_sizes; (void)n_in; (void)out_size;
    const int*   x      = (const int*)d_in[0];
    const float* h_init = (const float*)d_in[1];
    const float* embed  = (const float*)d_in[2];
    const float* Wx     = (const float*)d_in[3];
    const float* bx     = (const float*)d_in[4];
    const float* Wh     = (const float*)d_in[5];
    const float* bh     = (const float*)d_in[6];
    const float* Wo     = (const float*)d_in[7];
    const float* bo     = (const float*)d_in[8];

    float* out = (float*)d_out;
    float* h_e = out;                       // [B][T][H]
    float* y_e = out + (size_t)BT * Hh;     // [B][T][V]

    const int SMEM_P = 4 * TSZ * 4 + 128 * 8;               // 91136
    const int SMEM_R = SMEM_RF * 4;                         // 147456

    cudaFuncSetAttribute(gemm_k<true>,  cudaFuncAttributeMaxDynamicSharedMemorySize, SMEM_P);
    cudaFuncSetAttribute(gemm_k<false>, cudaFuncAttributeMaxDynamicSharedMemorySize, SMEM_P);
    cudaFuncSetAttribute(rnn_k,         cudaFuncAttributeMaxDynamicSharedMemorySize, SMEM_R);

    void* xp_ptr = nullptr;   cudaGetSymbolAddress(&xp_ptr, g_xp);
    void* hr_ptr = nullptr;   cudaGetSymbolAddress(&hr_ptr, g_hr);
    void* emb_ptr = nullptr;  cudaGetSymbolAddress(&emb_ptr, g_embr);
    void* wx_ptr = nullptr;   cudaGetSymbolAddress(&wx_ptr, g_Wxr);
    void* wo_ptr = nullptr;   cudaGetSymbolAddress(&wo_ptr, g_Wor);
    void* bs_ptr = nullptr;   cudaGetSymbolAddress(&bs_ptr, g_bsum);

    // 1. round+permute embed/Wx/Wo; reset flags; bx+bh; h_init -> g_h[0]
    prep_k<<<512, 256>>>(embed, Wx, Wo);
    init_k<<<128, 256>>>(h_init, bx, bh);
    // 2. xp[t][b][:] = embed_r[x[b][t]] @ Wx_r^T + (bx + bh)
    gemm_k<true><<<dim3(8, 512), 256, SMEM_P>>>((const float*)emb_ptr, x,
                                                (const float*)wx_ptr, (const float*)bs_ptr,
                                                (float*)xp_ptr);
    // 3. serial recurrence -> h_e (+ rounded copies)
    rnn_k<<<128, 256, SMEM_R>>>(Wh, h_e);
    // 4. y = h_r @ Wo_r^T + bo
    gemm_k<false><<<dim3(8, 512), 256, SMEM_P>>>((const float*)hr_ptr, nullptr,
                                                 (const float*)wo_ptr, bo, y_e);
}

// round 15
// speedup vs baseline: 1.4518x; 1.2611x over previous
#include <cuda_runtime.h>
#include <cstdint>
#include <math.h>

// Problem dims (fixed)
#define Bb 128
#define Tt 512
#define Hh 1024
#define BT (Bb*Tt)

// -------- device-global scratch ------------------------------------------
__device__ float g_eproj[1024 * 1024];     // embed @ Wx^T + (bx+bh)  (4 MB, L2-resident)
__device__ float g_hr[(size_t)BT * Hh];    // 256 MB rounded+permuted h [B][T][H]
__device__ float g_h[2][Bb * Hh];          // h double buffer (rounded+permuted)
__device__ float g_embr[1024 * 1024];      // rounded+permuted embed table
__device__ float g_Wxr[1024 * 1024];       // rounded+permuted Wx
__device__ float g_Wor[1024 * 1024];       // rounded+permuted Wo
__device__ float g_bsum[1024];             // bx + bh (fused step bias)
__device__ unsigned int g_flag[128 * 32];  // per-CTA publish counters, 128B apart

// -------- helpers --------------------------------------------------------
__device__ __forceinline__ uint32_t f2t(float x) {
    uint32_t u; asm("cvt.rna.tf32.f32 %0, %1;" : "=r"(u) : "f"(x));
    return u;
}
__device__ __forceinline__ float rndt(float x) { return __uint_as_float(f2t(x)); }
// k-pair interleave within 8-blocks: (j, j+4) -> positions (2j, 2j+1)
__device__ __forceinline__ int pig(int k) {
    int j = k & 7;
    return (k & ~7) | ((j < 4) ? (2 * j) : (2 * (j - 4) + 1));
}
__device__ __forceinline__ void cp16(float* s, const float* g) {
    uint32_t sa = (uint32_t)__cvta_generic_to_shared(s);
    asm volatile("cp.async.cg.shared.global [%0], [%1], 16;\n" :: "r"(sa), "l"(g));
}
__device__ __forceinline__ void cp_commit() { asm volatile("cp.async.commit_group;\n"); }
template<int N> __device__ __forceinline__ void cp_wait() {
    asm volatile("cp.async.wait_group %0;\n" :: "n"(N));
}
__device__ __forceinline__ void mma8(float* c, const uint32_t* a, const uint32_t* b) {
    asm volatile(
        "mma.sync.aligned.m16n8k8.row.col.f32.tf32.tf32.f32 "
        "{%0,%1,%2,%3},{%4,%5,%6,%7},{%8,%9},{%0,%1,%2,%3};"
        : "+f"(c[0]), "+f"(c[1]), "+f"(c[2]), "+f"(c[3])
        : "r"(a[0]), "r"(a[1]), "r"(a[2]), "r"(a[3]), "r"(b[0]), "r"(b[1]));
}
// fast tanh: 1 - 2/(exp(2x)+1) via ex2/rcp approx (saturates to +-1 at inf)
__device__ __forceinline__ float ftanh(float x) {
    float e;
    asm("ex2.approx.ftz.f32 %0, %1;" : "=f"(e) : "f"(x * 2.885390081777927f));
    float rc;
    asm("rcp.approx.ftz.f32 %0, %1;" : "=f"(rc) : "f"(e + 1.0f));
    return fmaf(-2.0f, rc, 1.0f);
}

// -------- prologue: round+permute embed, Wx, Wo --------------------------
__global__ void prep_k(const float* __restrict__ e, const float* __restrict__ wx,
                       const float* __restrict__ wo) {
    int st = gridDim.x * blockDim.x;
    for (int i = blockIdx.x * blockDim.x + threadIdx.x; i < 1024 * 1024; i += st) {
        int r = i >> 10, k = i & 1023;
        int d = (r << 10) | pig(k);
        g_embr[d] = rndt(e[i]);
        g_Wxr[d]  = rndt(wx[i]);
        g_Wor[d]  = rndt(wo[i]);
    }
}

__global__ void init_k(const float* __restrict__ h0, const float* __restrict__ bx,
                       const float* __restrict__ bh) {
    int i = blockIdx.x * blockDim.x + threadIdx.x;
    if (i < 128) g_flag[i * 32] = 0u;
    if (i < 1024) g_bsum[i] = bx[i] + bh[i];
    for (int j = i; j < Bb * Hh; j += gridDim.x * blockDim.x) {
        int r = j >> 10, k = j & 1023;
        g_h[0][(r << 10) | pig(k)] = rndt(h0[j]);
    }
}

// -------- phase GEMM: C[m][n] = sum_k A[m][k]*W[n][k] + bias[n] ----------
// Tile 128(M) x 128(N) x 32(K), 256 threads = 8 warps (2M x 4N), warp 64x32.
// 2-stage cp.async ring + occupancy 2 (cross-CTA overlap hides stage latency).
#define PS 44
#define TSZ 5632   // 128 rows x 44 per stage (A or B)

__device__ __forceinline__ void stage_p(const float* const* rp, const float* __restrict__ W,
                                        int n0, int k0, float* As, float* Bs, int tid) {
    #pragma unroll
    for (int j = 0; j < 4; j++) {                 // A: 128 rows x 32 floats
        int c = j * 256 + tid; int r = c >> 3, o = c & 7;
        cp16(As + r * PS + o * 4, rp[r] + k0 + o * 4);
    }
    #pragma unroll
    for (int j = 0; j < 4; j++) {                 // B: 128 rows x 32 floats
        int c = j * 256 + tid; int r = c >> 3, o = c & 7;
        cp16(Bs + r * PS + o * 4, W + (size_t)(n0 + r) * 1024 + k0 + o * 4);
    }
}

template<bool GATHER>
__global__ __launch_bounds__(256, 2) void gemm_k(const float* __restrict__ Ab,
                                                 const int* __restrict__ tok,
                                                 const float* __restrict__ W,
                                                 const float* __restrict__ bias,
                                                 float* __restrict__ C) {
    extern __shared__ float sm[];
    float* As = sm;                        // 2 x 5632
    float* Bs = sm + 2 * TSZ;              // 2 x 5632
    const float** rp = (const float**)(sm + 4 * TSZ);   // 128 ptrs

    const int tid = threadIdx.x;
    if (tid < 128) {
        if (GATHER) rp[tid] = Ab + (size_t)tok[tid * Tt + blockIdx.y] * 1024;
        else        rp[tid] = Ab + ((size_t)blockIdx.y * 128 + tid) * 1024;
    }
    __syncthreads();

    const int n0 = blockIdx.x * 128;
    const int lane = tid & 31, w = tid >> 5;
    const int g = lane >> 2, t4 = lane & 3;
    const int wm = (w >> 2) * 64, wn = (w & 3) * 32;

    float acc[4][4][4];
    #pragma unroll
    for (int a = 0; a < 4; a++)
        #pragma unroll
        for (int b = 0; b < 4; b++)
            #pragma unroll
            for (int c = 0; c < 4; c++) acc[a][b][c] = 0.f;

    stage_p(rp, W, n0, 0, As, Bs, tid);
    cp_commit();

    for (int ks = 0; ks < 32; ks++) {
        cp_wait<0>();
        __syncthreads();   // also orders: all reads of buf^1 done before restage
        if (ks < 31) {
            int nb = (ks + 1) & 1;
            stage_p(rp, W, n0, (ks + 1) * 32, As + nb * TSZ, Bs + nb * TSZ, tid);
            cp_commit();
        }
        const float* A_ = As + (ks & 1) * TSZ;
        const float* B_ = Bs + (ks & 1) * TSZ;
        #pragma unroll
        for (int kk = 0; kk < 32; kk += 8) {
            uint32_t a[4][4];
            #pragma unroll
            for (int mi = 0; mi < 4; mi++) {
                float2 p0 = *(const float2*)&A_[(wm + mi * 16 + g) * PS + kk + 2 * t4];
                float2 p1 = *(const float2*)&A_[(wm + mi * 16 + 8 + g) * PS + kk + 2 * t4];
                a[mi][0] = __float_as_uint(p0.x); a[mi][1] = __float_as_uint(p1.x);
                a[mi][2] = __float_as_uint(p0.y); a[mi][3] = __float_as_uint(p1.y);
            }
            #pragma unroll
            for (int ni = 0; ni < 4; ni++) {
                float2 q = *(const float2*)&B_[(wn + ni * 8 + g) * PS + kk + 2 * t4];
                uint32_t b[2] = { __float_as_uint(q.x), __float_as_uint(q.y) };
                #pragma unroll
                for (int mi = 0; mi < 4; mi++)
                    mma8(acc[mi][ni], a[mi], b);
            }
        }
    }

    const int m0 = blockIdx.y * 128;
    #pragma unroll
    for (int ni = 0; ni < 4; ni++) {
        int nc = n0 + wn + ni * 8 + 2 * t4;
        float b0 = bias[nc], b1 = bias[nc + 1];
        #pragma unroll
        for (int mi = 0; mi < 4; mi++) {
            int r0 = m0 + wm + mi * 16 + g;
            *(float2*)&C[(size_t)r0 * 1024 + nc] =
                make_float2(acc[mi][ni][0] + b0, acc[mi][ni][1] + b1);
            *(float2*)&C[(size_t)(r0 + 8) * 1024 + nc] =
                make_float2(acc[mi][ni][2] + b0, acc[mi][ni][3] + b1);
        }
    }
}

// -------- persistent recurrence kernel (R13 winner + eproj-gather xp) -----
// 128 CTAs = 4 independent M-groups x 32 N-CTAs, 256 thr (8 warps).
// Wh in registers; one-shot 4-chunk h staging; partials in own chunk-0.
// Decentralized hand-off (per-CTA flags, per-warp producer acquire).
// xp comes from the L2-resident eproj table via token gather (exact same
// bits as the old precomputed g_xp).
#define STG 36              // stage row stride (floats)
#define CHB (32 * STG)      // one chunk buffer = 1152 floats
#define CHW (4 * CHB)       // per-warp: 4 buffers = 4608 floats
#define SMEM_RF (8 * CHW)   // 36864 floats = 147456 B

__global__ __launch_bounds__(256, 1) void rnn_k(const float* __restrict__ Wh,
                                                const int* __restrict__ xtok,
                                                float* __restrict__ h_e) {
    extern __shared__ float sm[];
    float* Stg = sm;                       // 8 warps x 4 x (32x36)

    const int tid = threadIdx.x;
    const int nq = blockIdx.x & 31, mq = blockIdx.x >> 5;
    const int nb = nq * 32, mb = mq * 32;

    const int lane = tid & 31, w = tid >> 5;
    const int g = lane >> 2, t4 = lane & 3;
    const int kb = w * 128;
    float* SB = Stg + w * CHW;
    const int srow = lane >> 3, su = lane & 7;

    // this warp's 4 producer flags (group mq, producers 4w..4w+3); lane<4 polls
    unsigned int* pflag = &g_flag[((mq << 5) | (4 * w + (lane & 3))) * 32];
    unsigned int* myflag = &g_flag[blockIdx.x * 32];

    // ---- load Wh B-fragments into registers (rounded RNA; once) ----
    uint32_t bfr[4][16][2];
    #pragma unroll
    for (int ni = 0; ni < 4; ni++) {
        const float* Wrow = Wh + (size_t)(nb + ni * 8 + g) * 1024 + kb + t4;
        #pragma unroll
        for (int kf = 0; kf < 16; kf++) {
            bfr[ni][kf][0] = f2t(Wrow[kf * 8]);
            bfr[ni][kf][1] = f2t(Wrow[kf * 8 + 4]);
        }
    }

    // epilogue mapping (tid<128): row er, cols [gcb, gcb+8)
    const int er = tid & 31, eblk = tid >> 5;
    const int gr = mb + er, gcb = nb + eblk * 8;
    float4 xq0, xq1;
    if (tid < 128) {
        int tk = xtok[gr * Tt];                      // token for t=0
        xq0 = *(const float4*)&g_eproj[(size_t)tk * 1024 + gcb];
        xq1 = *(const float4*)&g_eproj[(size_t)tk * 1024 + gcb + 4];
    }
    __syncthreads();

    for (int t = 0; t < Tt; t++) {
        const float* hs = g_h[t & 1];
        float* hd = g_h[(t + 1) & 1];
        const float* gsrc = hs + (size_t)mb * 1024 + kb;

        // acquire this warp's 4 producers (flag >= t means h(t) published)
        if (t > 0 && lane < 4) {
            unsigned tgt = (unsigned)t, vv;
            do {
                asm volatile("ld.acquire.gpu.u32 %0, [%1];" : "=r"(vv) : "l"(pflag));
            } while (vv < tgt);
        }
        __syncwarp();

        float acc[2][4][4];
        #pragma unroll
        for (int a = 0; a < 2; a++)
            #pragma unroll
            for (int b = 0; b < 4; b++)
                #pragma unroll
                for (int c = 0; c < 4; c++) acc[a][b][c] = 0.f;

        // stage ALL 4 chunks now (one L2 round trip, 4 commit groups)
        #pragma unroll
        for (int cc = 0; cc < 4; cc++) {
            #pragma unroll
            for (int j = 0; j < 8; j++) {
                int r = srow + 4 * j;
                cp16(SB + cc * CHB + r * STG + su * 4,
                     gsrc + (size_t)r * 1024 + cc * 32 + su * 4);
            }
            cp_commit();
        }

        #pragma unroll
        for (int c = 0; c < 4; c++) {
            if (c == 0) cp_wait<3>();
            else if (c == 1) cp_wait<2>();
            else if (c == 2) cp_wait<1>();
            else cp_wait<0>();
            __syncwarp();
            const float* B_ = SB + c * CHB;
            #pragma unroll
            for (int kf = 0; kf < 4; kf++) {
                uint32_t a[2][4];
                #pragma unroll
                for (int mi = 0; mi < 2; mi++) {
                    float2 p0 = *(const float2*)&B_[(mi * 16 + g) * STG + kf * 8 + 2 * t4];
                    float2 p1 = *(const float2*)&B_[(mi * 16 + 8 + g) * STG + kf * 8 + 2 * t4];
                    a[mi][0] = __float_as_uint(p0.x); a[mi][1] = __float_as_uint(p1.x);
                    a[mi][2] = __float_as_uint(p0.y); a[mi][3] = __float_as_uint(p1.y);
                }
                #pragma unroll
                for (int ni = 0; ni < 4; ni++) {
                    mma8(acc[0][ni], a[0], bfr[ni][c * 4 + kf]);
                    mma8(acc[1][ni], a[1], bfr[ni][c * 4 + kf]);
                }
            }
        }

        // K-partials into own chunk-0 buffer (first consumed; warp-private)
        #pragma unroll
        for (int mi = 0; mi < 2; mi++)
            #pragma unroll
            for (int ni = 0; ni < 4; ni++) {
                int nc = ni * 8 + 2 * t4;
                *(float2*)&SB[(mi * 16 + g) * STG + nc] =
                    make_float2(acc[mi][ni][0], acc[mi][ni][1]);
                *(float2*)&SB[(mi * 16 + 8 + g) * STG + nc] =
                    make_float2(acc[mi][ni][2], acc[mi][ni][3]);
            }
        __syncthreads();   // (A) partials visible to reducing warps

        // reduce 8 partials + fast tanh; store NEXT-STATE hd; publish own flag
        float v[8], r[8];
        if (tid < 128) {
            float s[8] = {0.f,0.f,0.f,0.f,0.f,0.f,0.f,0.f};
            #pragma unroll
            for (int ww = 0; ww < 8; ww++) {
                const float* Rr = Stg + ww * CHW + er * STG + eblk * 8;
                float4 r0 = *(const float4*)&Rr[0];
                float4 r1 = *(const float4*)&Rr[4];
                s[0] += r0.x; s[1] += r0.y; s[2] += r0.z; s[3] += r0.w;
                s[4] += r1.x; s[5] += r1.y; s[6] += r1.z; s[7] += r1.w;
            }
            v[0] = ftanh(s[0] + xq0.x);
            v[1] = ftanh(s[1] + xq0.y);
            v[2] = ftanh(s[2] + xq0.z);
            v[3] = ftanh(s[3] + xq0.w);
            v[4] = ftanh(s[4] + xq1.x);
            v[5] = ftanh(s[5] + xq1.y);
            v[6] = ftanh(s[6] + xq1.z);
            v[7] = ftanh(s[7] + xq1.w);
            #pragma unroll
            for (int j = 0; j < 8; j++) r[j] = rndt(v[j]);
            *(float4*)&hd[(size_t)gr * 1024 + gcb]     = make_float4(r[0], r[4], r[1], r[5]);
            *(float4*)&hd[(size_t)gr * 1024 + gcb + 4] = make_float4(r[2], r[6], r[3], r[7]);

            // named barrier over the 128 storing threads, then release own flag
            asm volatile("bar.sync 1, 128;" ::: "memory");
            if (tid == 0)
                asm volatile("red.release.gpu.global.add.u32 [%0], %1;"
                             :: "l"(myflag), "r"(1u) : "memory");

            // stores nobody consumes this step + next xp gather (L2 hit)
            size_t orow = ((size_t)gr * Tt + t) * 1024 + gcb;
            *(float4*)&h_e[orow]     = make_float4(v[0], v[1], v[2], v[3]);
            *(float4*)&h_e[orow + 4] = make_float4(v[4], v[5], v[6], v[7]);
            *(float4*)&g_hr[orow]     = make_float4(r[0], r[4], r[1], r[5]);
            *(float4*)&g_hr[orow + 4] = make_float4(r[2], r[6], r[3], r[7]);
            if (t + 1 < Tt) {
                int tk = xtok[gr * Tt + t + 1];
                xq0 = *(const float4*)&g_eproj[(size_t)tk * 1024 + gcb];
                xq1 = *(const float4*)&g_eproj[(size_t)tk * 1024 + gcb + 4];
            }
        }
        __syncthreads();   // (B) reduce reads done -> chunk buffers reusable
    }
}

// -------- launch ---------------------------------------------------------
extern "C" void kernel_launch(void* const* d_in, const int* in_sizes, int n_in,
                              void* d_out, int out_size) {
    (void)in_sizes; (void)n_in; (void)out_size;
    const int*   x      = (const int*)d_in[0];
    const float* h_init = (const float*)d_in[1];
    const float* embed  = (const float*)d_in[2];
    const float* Wx     = (const float*)d_in[3];
    const float* bx     = (const float*)d_in[4];
    const float* Wh     = (const float*)d_in[5];
    const float* bh     = (const float*)d_in[6];
    const float* Wo     = (const float*)d_in[7];
    const float* bo     = (const float*)d_in[8];

    float* out = (float*)d_out;
    float* h_e = out;                       // [B][T][H]
    float* y_e = out + (size_t)BT * Hh;     // [B][T][V]

    const int SMEM_P = 4 * TSZ * 4 + 128 * 8;               // 91136
    const int SMEM_R = SMEM_RF * 4;                         // 147456

    cudaFuncSetAttribute(gemm_k<true>,  cudaFuncAttributeMaxDynamicSharedMemorySize, SMEM_P);
    cudaFuncSetAttribute(gemm_k<false>, cudaFuncAttributeMaxDynamicSharedMemorySize, SMEM_P);
    cudaFuncSetAttribute(rnn_k,         cudaFuncAttributeMaxDynamicSharedMemorySize, SMEM_R);

    void* ep_ptr = nullptr;   cudaGetSymbolAddress(&ep_ptr, g_eproj);
    void* hr_ptr = nullptr;   cudaGetSymbolAddress(&hr_ptr, g_hr);
    void* emb_ptr = nullptr;  cudaGetSymbolAddress(&emb_ptr, g_embr);
    void* wx_ptr = nullptr;   cudaGetSymbolAddress(&wx_ptr, g_Wxr);
    void* wo_ptr = nullptr;   cudaGetSymbolAddress(&wo_ptr, g_Wor);
    void* bs_ptr = nullptr;   cudaGetSymbolAddress(&bs_ptr, g_bsum);

    // 1. round+permute embed/Wx/Wo; reset flags; bx+bh; h_init -> g_h[0]
    prep_k<<<512, 256>>>(embed, Wx, Wo);
    init_k<<<128, 256>>>(h_init, bx, bh);
    // 2. eproj = embed_r @ Wx_r^T + (bx+bh)   [1024x1024 only — gather commutes]
    gemm_k<false><<<dim3(8, 8), 256, SMEM_P>>>((const float*)emb_ptr, nullptr,
                                               (const float*)wx_ptr, (const float*)bs_ptr,
                                               (float*)ep_ptr);
    // 3. serial recurrence -> h_e (+ rounded copies); xp = eproj[x[b,t]]
    rnn_k<<<128, 256, SMEM_R>>>(Wh, x, h_e);
    // 4. y = h_r @ Wo_r^T + bo
    gemm_k<false><<<dim3(8, 512), 256, SMEM_P>>>((const float*)hr_ptr, nullptr,
                                                 (const float*)wo_ptr, bo, y_e);
}